// round 13
// baseline (speedup 1.0000x reference)
#include <cuda_runtime.h>
#include <cstdint>

#define B_ 8
#define M_ 2048
#define N_ 2048
#define R_ 32

#define L1C 10.24f
#define L2C 10.24f
#define EPSC 1e-16f

// Scratch (device globals; no allocation allowed)
__device__ float g_bp[16 * B_ * R_ * R_];  // gram partials
__device__ float g_b[B_ * R_ * R_];        // reduced gram

// ---- bf16 helpers -------------------------------------------------------
__device__ __forceinline__ uint32_t pack2bf(float lo, float hi) {   // mem order [lo,hi]
    uint32_t r; asm("cvt.rn.bf16x2.f32 %0, %1, %2;" : "=r"(r) : "f"(hi), "f"(lo)); return r;
}
__device__ __forceinline__ uint16_t cvt1(float x) {
    uint16_t h; asm("cvt.rn.bf16.f32 %0, %1;" : "=h"(h) : "f"(x)); return h;
}
__device__ __forceinline__ float bf2f(uint16_t h) {
    return __uint_as_float(((uint32_t)h) << 16);
}
__device__ __forceinline__ void mma16816(float* c, const uint32_t* a, uint32_t b0, uint32_t b1) {
    asm volatile(
        "mma.sync.aligned.m16n8k16.row.col.f32.bf16.bf16.f32 "
        "{%0,%1,%2,%3}, {%4,%5,%6,%7}, {%8,%9}, {%0,%1,%2,%3};"
        : "+f"(c[0]), "+f"(c[1]), "+f"(c[2]), "+f"(c[3])
        : "r"(a[0]), "r"(a[1]), "r"(a[2]), "r"(a[3]), "r"(b0), "r"(b1));
}

// ======================= gram kernels =======================
#define GCHUNK 128
__global__ void gram_partial_kernel(const float* __restrict__ vin) {
    __shared__ float vs[GCHUNK][R_];
    int b = blockIdx.y, p = blockIdx.x, tid = threadIdx.x;
    const float4* src = (const float4*)(vin + ((size_t)b * N_ + p * GCHUNK) * R_);
    float4* dst = (float4*)&vs[0][0];
#pragma unroll
    for (int i = 0; i < 4; i++) dst[tid + 256 * i] = src[tid + 256 * i];
    __syncthreads();
    int r = tid >> 3, s4 = (tid & 7) * 4;
    float ax = 0.f, ay = 0.f, az = 0.f, aw = 0.f;
#pragma unroll 8
    for (int m = 0; m < GCHUNK; m++) {
        float vr = vs[m][r];
        float4 sv = *(const float4*)&vs[m][s4];
        ax += vr * sv.x; ay += vr * sv.y; az += vr * sv.z; aw += vr * sv.w;
    }
    float* o = g_bp + ((size_t)p * B_ + b) * (R_ * R_) + r * R_ + s4;
    o[0] = ax; o[1] = ay; o[2] = az; o[3] = aw;
}

__global__ void reduce_b_kernel() {
    int i = blockIdx.x * blockDim.x + threadIdx.x;
    if (i < B_ * R_ * R_) {
        float s = 0.f;
#pragma unroll
        for (int p = 0; p < 16; p++) s += g_bp[(size_t)p * (B_ * R_ * R_) + i];
        g_b[i] = s;
    }
}

// ======================= shared fragment compute =======================
template <int AST>
__device__ __forceinline__ void mma_kstep(const uint16_t* __restrict__ Ahi,
                                          const uint16_t* __restrict__ Alo,
                                          const uint16_t* __restrict__ Bhi,
                                          const uint16_t* __restrict__ Blo,
                                          int wrow, int g, int t4, int k16,
                                          float acc[4][4]) {
    uint32_t ah[4], al[4];
    int r0 = (wrow + g) * AST, r1 = (wrow + g + 8) * AST;
    int c0 = k16 + t4 * 2;
    ah[0] = *(const uint32_t*)&Ahi[r0 + c0];
    ah[1] = *(const uint32_t*)&Ahi[r1 + c0];
    ah[2] = *(const uint32_t*)&Ahi[r0 + c0 + 8];
    ah[3] = *(const uint32_t*)&Ahi[r1 + c0 + 8];
    al[0] = *(const uint32_t*)&Alo[r0 + c0];
    al[1] = *(const uint32_t*)&Alo[r1 + c0];
    al[2] = *(const uint32_t*)&Alo[r0 + c0 + 8];
    al[3] = *(const uint32_t*)&Alo[r1 + c0 + 8];
#pragma unroll
    for (int j = 0; j < 4; j++) {
        int nb = (j * 8 + g) * AST;
        uint32_t bh0 = *(const uint32_t*)&Bhi[nb + c0];
        uint32_t bh1 = *(const uint32_t*)&Bhi[nb + c0 + 8];
        uint32_t bl0 = *(const uint32_t*)&Blo[nb + c0];
        uint32_t bl1 = *(const uint32_t*)&Blo[nb + c0 + 8];
        mma16816(acc[j], ah, bh0, bh1);   // hi*hi
        mma16816(acc[j], ah, bl0, bl1);   // hi*lo
        mma16816(acc[j], al, bh0, bh1);   // lo*hi
    }
}

// Fused epilogue: acc -> smem res[128][33]; 128 threads run per-row CD; write out.
__device__ __forceinline__ void fused_cd_epilogue(
    float acc[4][4], float* __restrict__ res /* [128][33] smem */,
    const float (*bs)[R_], const float* __restrict__ inv,
    const float* __restrict__ uin_rows, float* __restrict__ uout_rows,
    int tid, int wrow, int g, int t4) {
#pragma unroll
    for (int j = 0; j < 4; j++) {
        int c = j * 8 + t4 * 2;
        res[(wrow + g) * 33 + c]     = acc[j][0];
        res[(wrow + g) * 33 + c + 1] = acc[j][1];
        res[(wrow + g + 8) * 33 + c]     = acc[j][2];
        res[(wrow + g + 8) * 33 + c + 1] = acc[j][3];
    }
    __syncthreads();

    if (tid < 128) {
        const float* ur = uin_rows + (size_t)tid * R_;
        const float* arow = res + tid * 33;
        float ureg[R_];
#pragma unroll
        for (int i = 0; i < 8; i++) {
            float4 t2 = *(const float4*)(ur + i * 4);
            ureg[4 * i + 0] = t2.x; ureg[4 * i + 1] = t2.y;
            ureg[4 * i + 2] = t2.z; ureg[4 * i + 3] = t2.w;
        }
#pragma unroll
        for (int r = 0; r < R_; r++) {
            float brr = bs[r][r];
            float d0 = 0.f, d1 = 0.f, d2 = 0.f, d3 = 0.f;
#pragma unroll
            for (int k = 0; k < R_; k += 4) {
                d0 += ureg[k + 0] * bs[k + 0][r];
                d1 += ureg[k + 1] * bs[k + 1][r];
                d2 += ureg[k + 2] * bs[k + 2][r];
                d3 += ureg[k + 3] * bs[k + 3][r];
            }
            float dot = (d0 + d1) + (d2 + d3);
            float z = arow[r] - (dot - ureg[r] * brr);
            float num = (z > L1C) ? (z - L1C) : ((z < -L1C) ? (z + L1C) : 0.0f);
            ureg[r] = (num + EPSC) * inv[r];
        }
        float* outr = uout_rows + (size_t)tid * R_;
#pragma unroll
        for (int i = 0; i < 8; i++) {
            float4 o = {ureg[4 * i + 0], ureg[4 * i + 1], ureg[4 * i + 2], ureg[4 * i + 3]};
            *(float4*)(outr + i * 4) = o;
        }
    }
}

// ======================= pass 1: uout = CD(x @ v, uin) =======================
// grid (M_/128, B_), 256 threads. KT=64, stride 72, double-buffered dynamic smem.
#define KT1 64
#define AST1 72
#define BUF1 46080   // Ahi 18432 | Alo 18432 | Bhi 4608 | Blo 4608
#define SMEM_P1 (2 * BUF1)

__global__ void __launch_bounds__(256)
hmma_xv_cd_kernel(const float* __restrict__ x, const float* __restrict__ v,
                  const float* __restrict__ uin, float* __restrict__ uout) {
    extern __shared__ char smc[];
    __shared__ float bs[R_][R_];
    __shared__ float inv[R_];

    int tid = threadIdx.x, wid = tid >> 5, lane = tid & 31;
    int g = lane >> 2, t4 = lane & 3, wrow = wid * 16;
    int b = blockIdx.y, m0 = blockIdx.x * 128;

    // load gram matrix; SYNC before reading it for inv (cross-thread elements!)
    {
        const float4* src = (const float4*)(g_b + (size_t)b * R_ * R_);
        ((float4*)&bs[0][0])[tid] = src[tid];
    }
    __syncthreads();
    if (tid < R_) inv[tid] = 1.0f / (bs[tid][tid] + L2C + EPSC);
    // inv visibility to the epilogue is ordered by the loop's later syncs.

    const float* xb = x + (size_t)b * M_ * N_;
    const float* vb = v + (size_t)b * N_ * R_;

    int arow = tid >> 4;        // 0..15, +16*i
    int aq   = tid & 15;        // float4 col group
    int bk   = tid >> 3;        // 0..31, +32*i
    int brq  = tid & 7;

    float acc[4][4] = {};

    float4 px[8], pv[2];
#pragma unroll
    for (int i = 0; i < 8; i++)
        px[i] = *(const float4*)(xb + (size_t)(m0 + arow + 16 * i) * N_ + aq * 4);
#pragma unroll
    for (int i = 0; i < 2; i++)
        pv[i] = *(const float4*)(vb + (size_t)(bk + 32 * i) * R_ + brq * 4);

    for (int t = 0; t < N_ / KT1; t++) {
        char* buf = smc + (t & 1) * BUF1;
        uint16_t* Ahi = (uint16_t*)(buf);
        uint16_t* Alo = (uint16_t*)(buf + 18432);
        uint16_t* Bhi = (uint16_t*)(buf + 36864);
        uint16_t* Blo = (uint16_t*)(buf + 41472);

        // stage A: fp32 -> bf16 hi/lo
#pragma unroll
        for (int i = 0; i < 8; i++) {
            int row = arow + 16 * i, k = aq * 4;
            uint32_t h01 = pack2bf(px[i].x, px[i].y);
            uint32_t h23 = pack2bf(px[i].z, px[i].w);
            float hx = __uint_as_float(h01 << 16), hy = __uint_as_float(h01 & 0xFFFF0000u);
            float hz = __uint_as_float(h23 << 16), hw = __uint_as_float(h23 & 0xFFFF0000u);
            uint32_t l01 = pack2bf(px[i].x - hx, px[i].y - hy);
            uint32_t l23 = pack2bf(px[i].z - hz, px[i].w - hw);
            *(uint2*)&Ahi[row * AST1 + k] = make_uint2(h01, h23);
            *(uint2*)&Alo[row * AST1 + k] = make_uint2(l01, l23);
        }
        // stage B transposed: v[k][r] -> B[r][k]
#pragma unroll
        for (int i = 0; i < 2; i++) {
            int k = bk + 32 * i;
            float vals[4] = {pv[i].x, pv[i].y, pv[i].z, pv[i].w};
#pragma unroll
            for (int e = 0; e < 4; e++) {
                int r = brq * 4 + e;
                uint16_t h = cvt1(vals[e]);
                Bhi[r * AST1 + k] = h;
                Blo[r * AST1 + k] = cvt1(vals[e] - bf2f(h));
            }
        }
        __syncthreads();

        if (t + 1 < N_ / KT1) {
            int kb = (t + 1) * KT1;
#pragma unroll
            for (int i = 0; i < 8; i++)
                px[i] = *(const float4*)(xb + (size_t)(m0 + arow + 16 * i) * N_ + kb + aq * 4);
#pragma unroll
            for (int i = 0; i < 2; i++)
                pv[i] = *(const float4*)(vb + (size_t)(kb + bk + 32 * i) * R_ + brq * 4);
        }

#pragma unroll
        for (int kk = 0; kk < KT1 / 16; kk++)
            mma_kstep<AST1>(Ahi, Alo, Bhi, Blo, wrow, g, t4, kk * 16, acc);
        // no trailing sync: next chunk writes the other buffer; reuse of this
        // buffer (t+2) is guarded by the sync inside chunk t+1.
    }

    __syncthreads();   // all MMA reads done before res overwrites buffer 0
    fused_cd_epilogue(acc, (float*)smc, bs, inv,
                      uin + ((size_t)b * M_ + m0) * R_,
                      uout + ((size_t)b * M_ + m0) * R_,
                      tid, wrow, g, t4);
}

// ======================= pass 2: vout = CD(x^T @ u, vin) =======================
// grid (N_/128, B_), 256 threads. KT=32, stride 40; fp32 transpose stage.
#define KT2 32
#define AST2 40
#define BUF2 42496   // Ahi 10240 | Alo 10240 | Bhi 2560 | Blo 2560 | stage 16896
#define SMEM_P2 (2 * BUF2)

__global__ void __launch_bounds__(256)
hmma_xtu_cd_kernel(const float* __restrict__ x, const float* __restrict__ u,
                   const float* __restrict__ vin, float* __restrict__ vout) {
    extern __shared__ char smc[];
    __shared__ float bs[R_][R_];
    __shared__ float inv[R_];

    int tid = threadIdx.x, wid = tid >> 5, lane = tid & 31;
    int g = lane >> 2, t4 = lane & 3, wrow = wid * 16;
    int b = blockIdx.y, n0 = blockIdx.x * 128;

    {
        const float4* src = (const float4*)(g_b + (size_t)b * R_ * R_);
        ((float4*)&bs[0][0])[tid] = src[tid];
    }
    __syncthreads();
    if (tid < R_) inv[tid] = 1.0f / (bs[tid][tid] + L2C + EPSC);

    const float* xb = x + (size_t)b * M_ * N_;
    const float* ub = u + (size_t)b * M_ * R_;

    int srow = tid >> 5;        // 0..7, +8*i
    int sq   = tid & 31;
    int bk   = tid >> 3;        // 0..31
    int brq  = tid & 7;
    int an   = tid >> 1;        // 0..127
    int ah_  = tid & 1;

    float acc[4][4] = {};

    float4 px[4], pu;
#pragma unroll
    for (int i = 0; i < 4; i++)
        px[i] = *(const float4*)(xb + (size_t)(srow + 8 * i) * N_ + n0 + sq * 4);
    pu = *(const float4*)(ub + (size_t)bk * R_ + brq * 4);

    for (int t = 0; t < N_ / KT2; t++) {
        char* buf = smc + (t & 1) * BUF2;
        uint16_t* Ahi = (uint16_t*)(buf);
        uint16_t* Alo = (uint16_t*)(buf + 10240);
        uint16_t* Bhi = (uint16_t*)(buf + 20480);
        uint16_t* Blo = (uint16_t*)(buf + 23040);
        float (*stage)[132] = (float (*)[132])(buf + 25600);

        // stage fp32 x chunk + B conversion
#pragma unroll
        for (int i = 0; i < 4; i++)
            *(float4*)&stage[srow + 8 * i][sq * 4] = px[i];
        {
            float vals[4] = {pu.x, pu.y, pu.z, pu.w};
#pragma unroll
            for (int e = 0; e < 4; e++) {
                int r = brq * 4 + e;
                uint16_t h = cvt1(vals[e]);
                Bhi[r * AST2 + bk] = h;
                Blo[r * AST2 + bk] = cvt1(vals[e] - bf2f(h));
            }
        }
        __syncthreads();

        if (t + 1 < N_ / KT2) {
            int mb = (t + 1) * KT2;
#pragma unroll
            for (int i = 0; i < 4; i++)
                px[i] = *(const float4*)(xb + (size_t)(mb + srow + 8 * i) * N_ + n0 + sq * 4);
            pu = *(const float4*)(ub + (size_t)(mb + bk) * R_ + brq * 4);
        }

        // transposed convert: A[n][k] bf16 hi/lo
#pragma unroll
        for (int j = 0; j < 4; j++) {
            int k0 = ah_ * 16 + j * 4;
            float a0 = stage[k0 + 0][an];
            float a1 = stage[k0 + 1][an];
            float a2 = stage[k0 + 2][an];
            float a3 = stage[k0 + 3][an];
            uint32_t h01 = pack2bf(a0, a1);
            uint32_t h23 = pack2bf(a2, a3);
            float hx = __uint_as_float(h01 << 16), hy = __uint_as_float(h01 & 0xFFFF0000u);
            float hz = __uint_as_float(h23 << 16), hw = __uint_as_float(h23 & 0xFFFF0000u);
            uint32_t l01 = pack2bf(a0 - hx, a1 - hy);
            uint32_t l23 = pack2bf(a2 - hz, a3 - hw);
            *(uint2*)&Ahi[an * AST2 + k0] = make_uint2(h01, h23);
            *(uint2*)&Alo[an * AST2 + k0] = make_uint2(l01, l23);
        }
        __syncthreads();

#pragma unroll
        for (int kk = 0; kk < KT2 / 16; kk++)
            mma_kstep<AST2>(Ahi, Alo, Bhi, Blo, wrow, g, t4, kk * 16, acc);
    }

    __syncthreads();
    fused_cd_epilogue(acc, (float*)smc, bs, inv,
                      vin + ((size_t)b * M_ + n0) * R_,
                      vout + ((size_t)b * M_ + n0) * R_,
                      tid, wrow, g, t4);
}

// ---------------------------------------------------------------------------
extern "C" void kernel_launch(void* const* d_in, const int* in_sizes, int n_in,
                              void* d_out, int out_size) {
    const float* x = (const float*)d_in[0];
    const float* u = (const float*)d_in[1];
    const float* v = (const float*)d_in[2];
    float* uout = (float*)d_out;
    float* vout = uout + (size_t)B_ * M_ * R_;

    cudaFuncSetAttribute(hmma_xv_cd_kernel, cudaFuncAttributeMaxDynamicSharedMemorySize, SMEM_P1);
    cudaFuncSetAttribute(hmma_xtu_cd_kernel, cudaFuncAttributeMaxDynamicSharedMemorySize, SMEM_P2);

    dim3 gg(16, B_);
    dim3 gt(M_ / 128, B_);      // 16 x 8 = 128 CTAs

    // Phase 1: u update (gram of v, then fused GEMM+CD)
    gram_partial_kernel<<<gg, 256>>>(v);
    reduce_b_kernel<<<32, 256>>>();
    hmma_xv_cd_kernel<<<gt, 256, SMEM_P1>>>(x, v, u, uout);

    // Phase 2: v update (gram of new u, then fused GEMM+CD)
    gram_partial_kernel<<<gg, 256>>>(uout);
    reduce_b_kernel<<<32, 256>>>();
    hmma_xtu_cd_kernel<<<gt, 256, SMEM_P2>>>(x, uout, v, vout);
}